// round 16
// baseline (speedup 1.0000x reference)
#include <cuda_runtime.h>
#include <cstdint>

// CRF NLL. feats (128,512,36) f32, transitions (36,36) f32, mask (128,512) i32,
// tags (128,512) i32 -> scalar f32.
// R15: ONE warp per batch (syncwarp instead of block barrier). Lane l<17 owns
// output pair (2l,2l+1). Per step: 9 broadcast LDS.128, 34 FFMA2 against
// persistent G pairs (8 accumulators, late pair isolated), dual fold, STS.64,
// WARPSYNC. Exactly len-1 steps. exp(feats)/60 via ex2 in register prefetch;
// C = len*log(60) exactly. Fused atomic reduction, self-resetting counters.

#define TT 36
#define BB 128
#define SS 512
#define CH 8
#define NT 32
#define LOG2E 1.4426950408889634f
#define NLOG2_60 -5.9068905956085185f
#define LN60 4.0943445622221004f

__device__ float g_sum;            // zero at load; reset by last block each launch
__device__ unsigned int g_count;

static __device__ __forceinline__ uint64_t pack2(float lo, float hi) {
    uint64_t r; asm("mov.b64 %0, {%1,%2};" : "=l"(r) : "f"(lo), "f"(hi)); return r;
}
static __device__ __forceinline__ void unpack2(uint64_t v, float& lo, float& hi) {
    asm("mov.b64 {%0,%1}, %2;" : "=f"(lo), "=f"(hi) : "l"(v));
}
static __device__ __forceinline__ uint64_t fma2(uint64_t a, uint64_t b, uint64_t c) {
    uint64_t d; asm("fma.rn.f32x2 %0, %1, %2, %3;" : "=l"(d) : "l"(a), "l"(b), "l"(c)); return d;
}
static __device__ __forceinline__ uint64_t add2(uint64_t a, uint64_t b) {
    uint64_t d; asm("add.rn.f32x2 %0, %1, %2;" : "=l"(d) : "l"(a), "l"(b)); return d;
}
static __device__ __forceinline__ float fexp60(float x) {
    // exp(x)/60 = ex2(x*log2(e) - log2(60))
    float t = __fmaf_rn(x, LOG2E, NLOG2_60);
    float r; asm("ex2.approx.f32 %0, %1;" : "=f"(r) : "f"(t));
    return r;
}

__global__ void __launch_bounds__(NT, 1)
crf_kernel(const float* __restrict__ feats,
           const float* __restrict__ trans,
           const int* __restrict__ mask,
           const int* __restrict__ tags,
           float* __restrict__ out)
{
    const int b = blockIdx.x;
    const int lane = threadIdx.x;
    const bool act = lane < 17;                    // owns output pair (2l, 2l+1)
    const int j0 = act ? 2 * lane : 0;
    const int j1 = j0 + 1;
    // active lanes store at their pair slot; idle lanes store zeros to pad
    // slots (34.. covers state 34/35 pad too, lane 17 writes floats 34,35).
    const int slot = act ? 2 * lane : (34 + 2 * (lane - 17));   // 34..64

    __shared__ __align__(16) float buf[2][68];     // ping-pong (floats 0..35 read)

    // ---- sequence length (contiguous-prefix mask) ----
    const int* mrow = mask + b * SS;
    int len = 0;
    for (int s = lane; s < SS; s += 32) len += mrow[s];
#pragma unroll
    for (int o = 16; o; o >>= 1) len += __shfl_xor_sync(0xffffffffu, len, o);

    const float* frow = feats + (size_t)b * SS * TT;

    // ---- persistent G pairs: G0[t] feeds output j0, G1[t] feeds j1 ----
    // input pairs t = 0..16 cover live input states 0..33 (START col = 0,
    // END never feeds back).
    uint64_t G0[17], G1[17];
#pragma unroll
    for (int t = 0; t < 17; t++) {
        float a0 = 0.f, a1 = 0.f, c0 = 0.f, c1 = 0.f;
        if (act) {
            a0 = __expf(trans[(2 * t) * TT + j0]); a1 = __expf(trans[(2 * t + 1) * TT + j0]);
            c0 = __expf(trans[(2 * t) * TT + j1]); c1 = __expf(trans[(2 * t + 1) * TT + j1]);
        }
        G0[t] = pack2(a0, a1);
        G1[t] = pack2(c0, c1);
    }
    const float ee0 = act ? __expf(trans[j0 * TT + (TT - 1)]) : 0.f;
    const float ee1 = act ? __expf(trans[j1 * TT + (TT - 1)]) : 0.f;

    // ---- init: w0_j = exp(trans[START][j]) * exp(feats[0][j])/60 ----
    float v0 = 0.f, v1 = 0.f;
    if (act) {
        v0 = __expf(trans[(TT - 2) * TT + j0]) * fexp60(frow[j0]);
        v1 = __expf(trans[(TT - 2) * TT + j1]) * fexp60(frow[j1]);
    }
    *(float2*)(buf[0] + slot) = make_float2(v0, v1);
    *(float2*)(buf[1] + slot) = make_float2(0.f, 0.f);
    __syncwarp();

    // ---- F prefetch (LDG.64 + ex2 off critical path), register double-buffer ----
    float2 pfe[CH];
#pragma unroll
    for (int k = 0; k < CH; k++) {
        float2 f = *(const float2*)(frow + (1 + k) * TT + j0);
        pfe[k] = make_float2(fexp60(f.x), fexp60(f.y));
    }

    // one chain step: read buf[rb], write buf[rb^1]; rb compile-time (k&1)
    auto step = [&](int rb, float2 f) {
        const ulonglong2* __restrict__ ub = (const ulonglong2*)buf[rb];
        ulonglong2 P0 = ub[0], P1 = ub[1], P2 = ub[2], P3 = ub[3], P4 = ub[4],
                   P5 = ub[5], P6 = ub[6], P7 = ub[7], P8 = ub[8];

        // out0 accums A..D (G0), out1 accums E..H (G1); pair 16 (P8.x,
        // last-arriving LDS) isolated as the final depth-1 op on A and E.
        uint64_t A = 0ull, B = 0ull, C = 0ull, D = 0ull;
        uint64_t E = 0ull, F = 0ull, G = 0ull, H = 0ull;
        A = fma2(P0.x, G0[0],  A);  E = fma2(P0.x, G1[0],  E);
        B = fma2(P0.y, G0[1],  B);  F = fma2(P0.y, G1[1],  F);
        C = fma2(P1.x, G0[2],  C);  G = fma2(P1.x, G1[2],  G);
        D = fma2(P1.y, G0[3],  D);  H = fma2(P1.y, G1[3],  H);
        A = fma2(P2.x, G0[4],  A);  E = fma2(P2.x, G1[4],  E);
        B = fma2(P2.y, G0[5],  B);  F = fma2(P2.y, G1[5],  F);
        C = fma2(P3.x, G0[6],  C);  G = fma2(P3.x, G1[6],  G);
        D = fma2(P3.y, G0[7],  D);  H = fma2(P3.y, G1[7],  H);
        A = fma2(P4.x, G0[8],  A);  E = fma2(P4.x, G1[8],  E);
        B = fma2(P4.y, G0[9],  B);  F = fma2(P4.y, G1[9],  F);
        C = fma2(P5.x, G0[10], C);  G = fma2(P5.x, G1[10], G);
        D = fma2(P5.y, G0[11], D);  H = fma2(P5.y, G1[11], H);
        A = fma2(P6.x, G0[12], A);  E = fma2(P6.x, G1[12], E);
        B = fma2(P6.y, G0[13], B);  F = fma2(P6.y, G1[13], F);
        C = fma2(P7.x, G0[14], C);  G = fma2(P7.x, G1[14], G);
        D = fma2(P7.y, G0[15], D);  H = fma2(P7.y, G1[15], H);
        // pre-fold the early accums while P8 is still in flight
        uint64_t S0p = add2(add2(B, C), D);
        uint64_t S1p = add2(add2(F, G), H);
        A = fma2(P8.x, G0[16], A);  E = fma2(P8.x, G1[16], E);
        uint64_t S0 = add2(A, S0p);
        uint64_t S1 = add2(E, S1p);
        float s0l, s0h, s1l, s1h;
        unpack2(S0, s0l, s0h);
        unpack2(S1, s1l, s1h);
        v0 = (s0l + s0h) * f.x;                    // idle lanes: G=0 -> v=0
        v1 = (s1l + s1h) * f.y;
        *(float2*)(buf[rb ^ 1] + slot) = make_float2(v0, v1);
        __syncwarp();
    };

    // ---- main loop: exactly len-1 steps, no per-step mask logic ----
    int base = 1;
    for (; base + CH <= len; base += CH) {
        float2 nfe[CH];
#pragma unroll
        for (int k = 0; k < CH; k++) {
            int s = base + CH + k; if (s > SS - 1) s = SS - 1;
            float2 f = *(const float2*)(frow + s * TT + j0);
            nfe[k] = make_float2(fexp60(f.x), fexp60(f.y));
        }
#pragma unroll
        for (int k = 0; k < CH; k++) step(k & 1, pfe[k]);
#pragma unroll
        for (int k = 0; k < CH; k++) pfe[k] = nfe[k];
    }
    // tail (< CH steps); condition uniform across the warp
#pragma unroll
    for (int k = 0; k < CH; k++)
        if (base + k < len) step(k & 1, pfe[k]);

    // ---- final: fwd_b = log(sum_j w_j * exp(trans[j][END])) + len*log(60) ----
    float p = v0 * ee0 + v1 * ee1;                 // idle lanes contribute 0
#pragma unroll
    for (int o = 16; o; o >>= 1) p += __shfl_xor_sync(0xffffffffu, p, o);

    // ---- gold score ----
    const int* trow = tags + b * SS;
    float gold = 0.f;
    for (int s = lane; s < SS; s += 32) {
        if (s < len) {
            int tg = trow[s];
            int pv = (s == 0) ? (TT - 2) : trow[s - 1];
            gold += frow[s * TT + tg] + trans[pv * TT + tg];
        }
    }
#pragma unroll
    for (int o = 16; o; o >>= 1) gold += __shfl_xor_sync(0xffffffffu, gold, o);

    if (lane == 0) {
        int endt = trow[len - 1];
        gold += trans[endt * TT + (TT - 1)];
        const float Ccorr = (float)len * LN60;
        const float nll_b = (__logf(p) + Ccorr) - gold;

        atomicAdd(&g_sum, nll_b);
        __threadfence();
        unsigned int old = atomicAdd(&g_count, 1u);
        if (old == BB - 1) {
            float total = atomicAdd(&g_sum, 0.0f);  // all adds visible via count protocol
            out[0] = total * (1.0f / (float)BB);
            g_sum = 0.0f;                            // self-reset for next graph replay
            g_count = 0u;
            __threadfence();
        }
    }
}

extern "C" void kernel_launch(void* const* d_in, const int* in_sizes, int n_in,
                              void* d_out, int out_size)
{
    const float* feats = (const float*)d_in[0];
    const float* trans = (const float*)d_in[1];
    const int*   mask  = (const int*)d_in[2];
    const int*   tags  = (const int*)d_in[3];
    (void)in_sizes; (void)n_in; (void)out_size;

    crf_kernel<<<BB, NT>>>(feats, trans, mask, tags, (float*)d_out);
}